// round 14
// baseline (speedup 1.0000x reference)
#include <cuda_runtime.h>

typedef unsigned long long ull;

#define T_STEPS  512
#define BATCH    64
#define EDIM     300
#define HDIM     512
#define BH       (BATCH * HDIM)
#define NBLK     128
#define NTHREADS 512

// strides in float4 units
#define WIH0_S   80     // 75 real + zero pad (chunk 4 reads f4 75..79)
#define WH_S     128    // exact
#define TILE_S   17     // 16 real + pad

// -------------------- persistent device scratch (no allocations) -----------
__device__ float g_h1[(size_t)T_STEPS * BH];   // layer-0 hidden, all t
__device__ float g_h2[(size_t)T_STEPS * BH];   // layer-1 hidden, all t
__device__ float g_zero[BH];                   // never written: stays 0
__device__ float g_pooled[T_STEPS * HDIM];     // mean over batch of h2
__device__ unsigned g_flags[NBLK];             // per-CTA monotonic step flags

// -------------------- helpers ---------------------------------------------
__device__ __forceinline__ void fma2(ull& acc, ull a, ull b) {
    asm volatile("fma.rn.f32x2 %0, %1, %2, %0;" : "+l"(acc) : "l"(a), "l"(b));
}
__device__ __forceinline__ float hsum2(ull v) {
    return __uint_as_float((unsigned)v) + __uint_as_float((unsigned)(v >> 32));
}
__device__ __forceinline__ float sigf(float x) { return 1.0f / (1.0f + expf(-x)); }

// hsum + reduce over the 8 kq lanes (lane bits 0-2)
__device__ __forceinline__ float redq(ull a) {
    float f = hsum2(a);
    f += __shfl_xor_sync(0xffffffffu, f, 1);
    f += __shfl_xor_sync(0xffffffffu, f, 2);
    f += __shfl_xor_sync(0xffffffffu, f, 4);
    return f;
}

// ---- 8 batches x 3 rows, thread K-slice = f4 {kq, kq+8} (conflict-free) ----
__device__ __forceinline__ void mac3x8(const ulonglong2* __restrict__ t,
    const ulonglong2* __restrict__ w0, const ulonglong2* __restrict__ w1,
    const ulonglong2* __restrict__ w2,
    ull A0[8], ull A1[8], ull A2[8])
{
#pragma unroll
    for (int i = 0; i < 2; i++) {
        const int o = 8 * i;
        ulonglong2 v0 = w0[o], v1 = w1[o], v2 = w2[o];
#pragma unroll
        for (int half = 0; half < 2; half++) {
            const int hb = half * 4;
            ulonglong2 h0 = t[(hb + 0) * TILE_S + o];
            ulonglong2 h1 = t[(hb + 1) * TILE_S + o];
            ulonglong2 h2 = t[(hb + 2) * TILE_S + o];
            ulonglong2 h3 = t[(hb + 3) * TILE_S + o];
            fma2(A0[hb+0], h0.x, v0.x); fma2(A0[hb+0], h0.y, v0.y);
            fma2(A0[hb+1], h1.x, v0.x); fma2(A0[hb+1], h1.y, v0.y);
            fma2(A0[hb+2], h2.x, v0.x); fma2(A0[hb+2], h2.y, v0.y);
            fma2(A0[hb+3], h3.x, v0.x); fma2(A0[hb+3], h3.y, v0.y);
            fma2(A1[hb+0], h0.x, v1.x); fma2(A1[hb+0], h0.y, v1.y);
            fma2(A1[hb+1], h1.x, v1.x); fma2(A1[hb+1], h1.y, v1.y);
            fma2(A1[hb+2], h2.x, v1.x); fma2(A1[hb+2], h2.y, v1.y);
            fma2(A1[hb+3], h3.x, v1.x); fma2(A1[hb+3], h3.y, v1.y);
            fma2(A2[hb+0], h0.x, v2.x); fma2(A2[hb+0], h0.y, v2.y);
            fma2(A2[hb+1], h1.x, v2.x); fma2(A2[hb+1], h1.y, v2.y);
            fma2(A2[hb+2], h2.x, v2.x); fma2(A2[hb+2], h2.y, v2.y);
            fma2(A2[hb+3], h3.x, v2.x); fma2(A2[hb+3], h3.y, v2.y);
        }
    }
}

__device__ __forceinline__ void stage128(float4* dst, const float* W, int j0, int tid) {
    for (int idx = tid; idx < 12 * WH_S; idx += NTHREADS) {
        int m = idx >> 7, f4 = idx & 127;
        int g = m >> 2, u = m & 3;
        dst[idx] = reinterpret_cast<const float4*>(W + (size_t)(g * HDIM + j0 + u) * HDIM)[f4];
    }
}

// ========  fused 2-layer GRU, layer-specialized halves, lag-2 pipeline  =====
// Thread = (bg in 8, L in 2, jj in 4, kq in 8): lane = jj*8+kq, warp = bg*2+L.
// L=0 half computes layer0 at t=s; L=1 half computes layer1 at t=s-2.
// Each half owns its tile double-buffer + named barrier (bar.sync L+1, 256).
// Halves couple only at the grid flag-wait and the arrival syncthreads.
__global__ void __launch_bounds__(NTHREADS, 1)
gru_fused(const int* __restrict__ texts, const float* __restrict__ emb,
          const float* __restrict__ Wih0, const float* __restrict__ Whh0,
          const float* __restrict__ bih0, const float* __restrict__ bhh0,
          const float* __restrict__ Wih1, const float* __restrict__ Whh1,
          const float* __restrict__ bih1, const float* __restrict__ bhh1)
{
    extern __shared__ float4 smem[];
    float4* w_ih0  = smem;                              // 960 f4
    float4* w_hh0  = smem + 12 * WIH0_S;                // 1536 f4
    float4* w_ih1  = w_hh0 + 12 * WH_S;
    float4* w_hh1  = w_ih1 + 12 * WH_S;
    float4* tilesA = w_hh1 + 12 * WH_S;                 // L0: 2 x 1088 f4
    float4* tilesB = tilesA + 2 * 1088;                 // L1: 2 x 1088 f4
    __shared__ float pool_sh[32];
    __shared__ int   tok_sh[BATCH];

    const int tid = threadIdx.x;
    const int bid = blockIdx.x;
    const int j0  = bid * 4;
    const int kq  = tid & 7;            // lane bits 0-2: K-slice
    const int jj  = (tid >> 3) & 3;     // lane bits 3-4: unit
    const int L   = (tid >> 5) & 1;     // warp bit 0: layer
    const int bg  = tid >> 6;           // batch group (8 batches)
    const int j   = j0 + jj;
    const int b0  = bg * 8;
    const int htid = bg * 32 + (tid & 31);   // linear id within my half (0..255)

    const unsigned base = *(volatile unsigned*)&g_flags[bid];

    // ---- stage weights (once, all 512 threads) ----
    for (int idx = tid; idx < 12 * WIH0_S; idx += NTHREADS) {
        int m = idx / WIH0_S, f4 = idx - m * WIH0_S;
        int g = m >> 2, u = m & 3;
        float4 v = make_float4(0.f, 0.f, 0.f, 0.f);
        if (f4 < 75)
            v = reinterpret_cast<const float4*>(Wih0 + (size_t)(g * HDIM + j0 + u) * EDIM)[f4];
        w_ih0[idx] = v;
    }
    stage128(w_hh0, Whh0, j0, tid);
    stage128(w_ih1, Wih1, j0, tid);
    stage128(w_hh1, Whh1, j0, tid);
    __syncthreads();

    // ---- per-layer constants / pointers ----
    const float* bihL = L ? bih1 : bih0;
    const float* bhhL = L ? bhh1 : bhh0;
    const float br = bihL[j] + bhhL[j];
    const float bz = bihL[HDIM + j] + bhhL[HDIM + j];
    const float bx = bihL[2 * HDIM + j];
    const float bh = bhhL[2 * HDIM + j];

    const float4* w_in  = L ? w_ih1 : w_ih0;
    const int     WS_IN = L ? WH_S  : WIH0_S;
    const float4* w_rec = L ? w_hh1 : w_hh0;
    const ulonglong2* pInR  = (const ulonglong2*)w_in  + (0 + jj) * WS_IN + kq;
    const ulonglong2* pInZ  = (const ulonglong2*)w_in  + (4 + jj) * WS_IN + kq;
    const ulonglong2* pInN  = (const ulonglong2*)w_in  + (8 + jj) * WS_IN + kq;
    const ulonglong2* pRecR = (const ulonglong2*)w_rec + (0 + jj) * WH_S + kq;
    const ulonglong2* pRecZ = (const ulonglong2*)w_rec + (4 + jj) * WH_S + kq;
    const ulonglong2* pRecN = (const ulonglong2*)w_rec + (8 + jj) * WH_S + kq;

    float4* const myTiles = L ? tilesB : tilesA;

    // per-thread STS destinations (4 float4 per chunk, within my half)
    int dof[4];
#pragma unroll
    for (int i = 0; i < 4; i++) {
        int idx = htid + i * 256;
        dof[i] = (idx >> 4) * TILE_S + (idx & 15);
    }

#define HBAR() asm volatile("bar.sync %0, 256;" :: "r"(L + 1) : "memory")
#define PRE_EMB(CC) do { int c_ = (CC);                                          \
    _Pragma("unroll") for (int i = 0; i < 4; i++) {                              \
        int idx = htid + i * 256; int rr = idx >> 4, f4 = idx & 15;              \
        int gf4 = c_ * 16 + f4;                                                  \
        float4 v = make_float4(0.f, 0.f, 0.f, 0.f);                              \
        if (gf4 < 75)                                                            \
            v = reinterpret_cast<const float4*>(emb + (size_t)tok_sh[rr] * EDIM)[gf4]; \
        pr[i] = v; } } while (0)
#define PRE_H(SRC, CC) do { int c_ = (CC);                                       \
    _Pragma("unroll") for (int i = 0; i < 4; i++) {                              \
        int idx = htid + i * 256; int rr = idx >> 4, f4 = idx & 15;              \
        pr[i] = (SRC)[rr * 128 + c_ * 16 + f4]; } } while (0)
#define STAGE() do {                                                             \
    float4* buf_ = myTiles + (qi & 1) * 1088;                                    \
    _Pragma("unroll") for (int i = 0; i < 4; i++) buf_[dof[i]] = pr[i];          \
    HBAR(); tp = (const ulonglong2*)buf_ + b0 * TILE_S + kq; } while (0)

    for (int s = 0; s <= T_STEPS + 1; s++) {
        const bool me0 = (L == 0) && (s < T_STEPS);       // layer0 @ t = s
        const bool me1 = (L == 1) && (s >= 2);            // layer1 @ t = s-2

        ull AR[8], AZ[8], AX[8], AH[8];
#pragma unroll
        for (int i = 0; i < 8; i++) { AR[i] = AZ[i] = AX[i] = AH[i] = 0ull; }

        float4 pr[4];
        const ulonglong2* tp;
        int qi = 0;

        // recurrent-input pointers (layer-dependent)
        const float* hprev = 0;
        if (me0) hprev = (s == 0) ? g_zero : g_h1 + (size_t)(s - 1) * BH;
        if (me1) hprev = (s <= 2) ? g_zero : g_h2 + (size_t)(s - 3) * BH;
        const float4* hprev4 = (const float4*)hprev;

        // ---- pre-wait phase ----
        if (me0) {       // embedding projection (needs nothing from other CTAs)
            if (htid < BATCH) tok_sh[htid] = texts[s * BATCH + htid];
            HBAR();
            PRE_EMB(0);
            for (int c = 0; c < 5; c++) {
                STAGE();
                if (c < 4) PRE_EMB(c + 1);
                mac3x8(tp, pInR + c * 16, pInZ + c * 16, pInN + c * 16, AR, AZ, AX);
                qi++;
            }
        }
        if (me1) {       // input projection from h1[s-2] (safe: published @ step s-2)
            const float4* xs = (const float4*)(g_h1 + (size_t)(s - 2) * BH);
            PRE_H(xs, 0);
            for (int c = 0; c < 8; c++) {
                STAGE();
                if (c < 7) PRE_H(xs, c + 1);
                else       PRE_H(hprev4, 0);   // prefetch h2[s-3]: also pre-wait-safe
                mac3x8(tp, pInR + c * 16, pInZ + c * 16, pInN + c * 16, AR, AZ, AX);
                qi++;
            }
        }

        // ---- grid wait: h1[s-1] (and older) now published by all CTAs ----
        if (tid < NBLK) {
            unsigned tgt = base + (unsigned)s;
            while ((int)(*(volatile unsigned*)&g_flags[tid] - tgt) < 0) { }
            __threadfence();
        }
        __syncthreads();

        // ---- post-wait phase: recurrent MACs ----
        if (me0) {
            PRE_H(hprev4, 0);
            for (int c = 0; c < 8; c++) {
                STAGE();
                if (c < 7) PRE_H(hprev4, c + 1);
                mac3x8(tp, pRecR + c * 16, pRecZ + c * 16, pRecN + c * 16, AR, AZ, AH);
                qi++;
            }
#pragma unroll
            for (int i = 0; i < 8; i++) {
                float fr = redq(AR[i]);
                float fz = redq(AZ[i]);
                float fx = redq(AX[i]);
                float fh = redq(AH[i]);
                if (kq == 0) {
                    int b = b0 + i;
                    float r = sigf(fr + br);
                    float z = sigf(fz + bz);
                    float n = tanhf(fx + bx + r * (fh + bh));
                    float hp = hprev[b * HDIM + j];
                    g_h1[(size_t)s * BH + b * HDIM + j] = (1.0f - z) * n + z * hp;
                }
            }
        }
        if (me1) {
            for (int c = 0; c < 8; c++) {
                STAGE();                       // pr preloaded (chunk 0 from pre-phase)
                if (c < 7) PRE_H(hprev4, c + 1);
                mac3x8(tp, pRecR + c * 16, pRecZ + c * 16, pRecN + c * 16, AR, AZ, AH);
                qi++;
            }
            float psum = 0.f;
#pragma unroll
            for (int i = 0; i < 8; i++) {
                float fr = redq(AR[i]);
                float fz = redq(AZ[i]);
                float fx = redq(AX[i]);
                float fh = redq(AH[i]);
                if (kq == 0) {
                    int b = b0 + i;
                    float r = sigf(fr + br);
                    float z = sigf(fz + bz);
                    float n = tanhf(fx + bx + r * (fh + bh));
                    float hp = hprev[b * HDIM + j];
                    float hnew = (1.0f - z) * n + z * hp;
                    g_h2[(size_t)(s - 2) * BH + b * HDIM + j] = hnew;
                    psum += hnew;
                }
            }
            if (kq == 0) pool_sh[bg * 4 + jj] = psum;
            HBAR();
            if (bg == 0 && kq == 0) {          // 4 threads, one per jj
                float sum = 0.f;
#pragma unroll
                for (int g = 0; g < 8; g++) sum += pool_sh[g * 4 + jj];
                g_pooled[(s - 2) * HDIM + j0 + jj] = sum * (1.0f / BATCH);
            }
        }

        // ---- arrive ----
        __threadfence();
        __syncthreads();
        if (tid == 0)
            *(volatile unsigned*)&g_flags[bid] = base + (unsigned)s + 1u;
    }
#undef HBAR
#undef PRE_EMB
#undef PRE_H
#undef STAGE
}

// =====================  final FC: [T,H] @ [L,H]^T + b  ======================
__global__ void fc_kernel(const float* __restrict__ fcW, const float* __restrict__ fcb,
                          float* __restrict__ out)
{
    int t    = blockIdx.x;
    int l    = threadIdx.x >> 5;   // 5 warps -> 5 outputs
    int lane = threadIdx.x & 31;
    const float* p = g_pooled + t * HDIM;
    const float* w = fcW + l * HDIM;
    float s = 0.f;
#pragma unroll 4
    for (int k = lane; k < HDIM; k += 32) s += p[k] * w[k];
#pragma unroll
    for (int o = 16; o; o >>= 1) s += __shfl_xor_sync(0xffffffffu, s, o);
    if (lane == 0) out[t * 5 + l] = s + fcb[l];
}

// ===========================================================================
extern "C" void kernel_launch(void* const* d_in, const int* in_sizes, int n_in,
                              void* d_out, int out_size) {
    (void)in_sizes; (void)n_in; (void)out_size;
    const int*   texts = (const int*)  d_in[0];
    const float* emb   = (const float*)d_in[1];
    const float* Wih0  = (const float*)d_in[2];
    const float* Whh0  = (const float*)d_in[3];
    const float* bih0  = (const float*)d_in[4];
    const float* bhh0  = (const float*)d_in[5];
    const float* Wih1  = (const float*)d_in[6];
    const float* Whh1  = (const float*)d_in[7];
    const float* bih1  = (const float*)d_in[8];
    const float* bhh1  = (const float*)d_in[9];
    const float* fcW   = (const float*)d_in[10];
    const float* fcb   = (const float*)d_in[11];
    float* out = (float*)d_out;

    // 960 + 3*1536 + 4*1088 = 9920 float4 = 158,720 B dynamic SMEM
    const int smemB = (12 * WIH0_S + 3 * 12 * WH_S + 4 * 1088) * 16;
    cudaFuncSetAttribute(gru_fused, cudaFuncAttributeMaxDynamicSharedMemorySize, smemB);

    gru_fused<<<NBLK, NTHREADS, smemB>>>(texts, emb,
                                         Wih0, Whh0, bih0, bhh0,
                                         Wih1, Whh1, bih1, bhh1);
    fc_kernel<<<T_STEPS, 160>>>(fcW, fcb, out);
}

// round 15
// speedup vs baseline: 1.7125x; 1.7125x over previous
#include <cuda_runtime.h>
#include <cstdint>

typedef unsigned long long ull;

#define T_STEPS  512
#define BATCH    64
#define EDIM     300
#define HDIM     512
#define BH       (BATCH * HDIM)
#define NBLK     128
#define NTHREADS 256

// strides in float4 units
#define WIH0_S   96     // 75 real + zero pad (3 chunks x 32 f4)
#define WH_S     128    // exact (4 chunks x 32 f4)
#define TILE_S   33     // 32 real + 1 pad
#define TILE_F4  (64 * TILE_S)   // 2112 f4 per buffer

// -------------------- persistent device scratch (no allocations) -----------
__device__ float g_h1[(size_t)T_STEPS * BH];   // layer-0 hidden, all t
__device__ float g_h2[(size_t)T_STEPS * BH];   // layer-1 hidden, all t
__device__ float g_zero[BH];                   // never written: stays 0
__device__ float g_pooled[T_STEPS * HDIM];     // mean over batch of h2
__device__ unsigned g_flags[NBLK];             // per-CTA monotonic step flags

// -------------------- helpers ---------------------------------------------
__device__ __forceinline__ void fma2(ull& acc, ull a, ull b) {
    asm volatile("fma.rn.f32x2 %0, %1, %2, %0;" : "+l"(acc) : "l"(a), "l"(b));
}
__device__ __forceinline__ float hsum2(ull v) {
    return __uint_as_float((unsigned)v) + __uint_as_float((unsigned)(v >> 32));
}
__device__ __forceinline__ float sigf(float x) { return 1.0f / (1.0f + expf(-x)); }

__device__ __forceinline__ float redq(ull a) {
    float f = hsum2(a);
    f += __shfl_xor_sync(0xffffffffu, f, 1);
    f += __shfl_xor_sync(0xffffffffu, f, 2);
    f += __shfl_xor_sync(0xffffffffu, f, 4);
    return f;
}

// cp.async: 16B GMEM->SMEM, zero-fill beyond src_sz bytes
__device__ __forceinline__ void cp16(uint32_t dst, const void* src, unsigned src_sz) {
    asm volatile("cp.async.cg.shared.global [%0], [%1], 16, %2;"
                 :: "r"(dst), "l"(src), "r"(src_sz) : "memory");
}
__device__ __forceinline__ void cp_commit() {
    asm volatile("cp.async.commit_group;" ::: "memory");
}
__device__ __forceinline__ void cp_wait0() {
    asm volatile("cp.async.wait_group 0;" ::: "memory");
}

// ---- 8 batches x 3 rows, 128-wide chunk: thread K-slice f4 {kq,+8,+16,+24} --
__device__ __forceinline__ void mac3x8(const ulonglong2* __restrict__ t,
    const ulonglong2* __restrict__ w0, const ulonglong2* __restrict__ w1,
    const ulonglong2* __restrict__ w2,
    ull A0[8], ull A1[8], ull A2[8])
{
#pragma unroll
    for (int i = 0; i < 4; i++) {
        const int o = 8 * i;
        ulonglong2 v0 = w0[o], v1 = w1[o], v2 = w2[o];
#pragma unroll
        for (int half = 0; half < 2; half++) {
            const int hb = half * 4;
            ulonglong2 h0 = t[(hb + 0) * TILE_S + o];
            ulonglong2 h1 = t[(hb + 1) * TILE_S + o];
            ulonglong2 h2 = t[(hb + 2) * TILE_S + o];
            ulonglong2 h3 = t[(hb + 3) * TILE_S + o];
            fma2(A0[hb+0], h0.x, v0.x); fma2(A0[hb+0], h0.y, v0.y);
            fma2(A0[hb+1], h1.x, v0.x); fma2(A0[hb+1], h1.y, v0.y);
            fma2(A0[hb+2], h2.x, v0.x); fma2(A0[hb+2], h2.y, v0.y);
            fma2(A0[hb+3], h3.x, v0.x); fma2(A0[hb+3], h3.y, v0.y);
            fma2(A1[hb+0], h0.x, v1.x); fma2(A1[hb+0], h0.y, v1.y);
            fma2(A1[hb+1], h1.x, v1.x); fma2(A1[hb+1], h1.y, v1.y);
            fma2(A1[hb+2], h2.x, v1.x); fma2(A1[hb+2], h2.y, v1.y);
            fma2(A1[hb+3], h3.x, v1.x); fma2(A1[hb+3], h3.y, v1.y);
            fma2(A2[hb+0], h0.x, v2.x); fma2(A2[hb+0], h0.y, v2.y);
            fma2(A2[hb+1], h1.x, v2.x); fma2(A2[hb+1], h1.y, v2.y);
            fma2(A2[hb+2], h2.x, v2.x); fma2(A2[hb+2], h2.y, v2.y);
            fma2(A2[hb+3], h3.x, v2.x); fma2(A2[hb+3], h3.y, v2.y);
        }
    }
}

// ---- 8 batches x 6 rows (layer0-recurrent + layer1-input share the tile) --
__device__ __forceinline__ void mac6x8(const ulonglong2* __restrict__ t,
    const ulonglong2* __restrict__ w0, const ulonglong2* __restrict__ w1,
    const ulonglong2* __restrict__ w2, const ulonglong2* __restrict__ w3,
    const ulonglong2* __restrict__ w4, const ulonglong2* __restrict__ w5,
    ull A0[8], ull A1[8], ull A2[8], ull B0[8], ull B1[8], ull B2[8])
{
#pragma unroll
    for (int i = 0; i < 4; i++) {
        const int o = 8 * i;
        ulonglong2 v0 = w0[o], v1 = w1[o], v2 = w2[o];
        ulonglong2 v3 = w3[o], v4 = w4[o], v5 = w5[o];
#pragma unroll
        for (int half = 0; half < 2; half++) {
            const int hb = half * 4;
            ulonglong2 h0 = t[(hb + 0) * TILE_S + o];
            ulonglong2 h1 = t[(hb + 1) * TILE_S + o];
            ulonglong2 h2 = t[(hb + 2) * TILE_S + o];
            ulonglong2 h3 = t[(hb + 3) * TILE_S + o];
            fma2(A0[hb+0], h0.x, v0.x); fma2(A0[hb+0], h0.y, v0.y);
            fma2(A0[hb+1], h1.x, v0.x); fma2(A0[hb+1], h1.y, v0.y);
            fma2(A0[hb+2], h2.x, v0.x); fma2(A0[hb+2], h2.y, v0.y);
            fma2(A0[hb+3], h3.x, v0.x); fma2(A0[hb+3], h3.y, v0.y);
            fma2(A1[hb+0], h0.x, v1.x); fma2(A1[hb+0], h0.y, v1.y);
            fma2(A1[hb+1], h1.x, v1.x); fma2(A1[hb+1], h1.y, v1.y);
            fma2(A1[hb+2], h2.x, v1.x); fma2(A1[hb+2], h2.y, v1.y);
            fma2(A1[hb+3], h3.x, v1.x); fma2(A1[hb+3], h3.y, v1.y);
            fma2(A2[hb+0], h0.x, v2.x); fma2(A2[hb+0], h0.y, v2.y);
            fma2(A2[hb+1], h1.x, v2.x); fma2(A2[hb+1], h1.y, v2.y);
            fma2(A2[hb+2], h2.x, v2.x); fma2(A2[hb+2], h2.y, v2.y);
            fma2(A2[hb+3], h3.x, v2.x); fma2(A2[hb+3], h3.y, v2.y);
            fma2(B0[hb+0], h0.x, v3.x); fma2(B0[hb+0], h0.y, v3.y);
            fma2(B0[hb+1], h1.x, v3.x); fma2(B0[hb+1], h1.y, v3.y);
            fma2(B0[hb+2], h2.x, v3.x); fma2(B0[hb+2], h2.y, v3.y);
            fma2(B0[hb+3], h3.x, v3.x); fma2(B0[hb+3], h3.y, v3.y);
            fma2(B1[hb+0], h0.x, v4.x); fma2(B1[hb+0], h0.y, v4.y);
            fma2(B1[hb+1], h1.x, v4.x); fma2(B1[hb+1], h1.y, v4.y);
            fma2(B1[hb+2], h2.x, v4.x); fma2(B1[hb+2], h2.y, v4.y);
            fma2(B1[hb+3], h3.x, v4.x); fma2(B1[hb+3], h3.y, v4.y);
            fma2(B2[hb+0], h0.x, v5.x); fma2(B2[hb+0], h0.y, v5.y);
            fma2(B2[hb+1], h1.x, v5.x); fma2(B2[hb+1], h1.y, v5.y);
            fma2(B2[hb+2], h2.x, v5.x); fma2(B2[hb+2], h2.y, v5.y);
            fma2(B2[hb+3], h3.x, v5.x); fma2(B2[hb+3], h3.y, v5.y);
        }
    }
}

__device__ __forceinline__ void stage128(float4* dst, const float* W, int j0, int tid) {
    for (int idx = tid; idx < 12 * WH_S; idx += NTHREADS) {
        int m = idx >> 7, f4 = idx & 127;
        int g = m >> 2, u = m & 3;
        dst[idx] = reinterpret_cast<const float4*>(W + (size_t)(g * HDIM + j0 + u) * HDIM)[f4];
    }
}

// ===========  fused 2-layer GRU (R13 layout) + cp.async 128-wide chunks  ====
// Thread = (bg in 8, jj in 4, kq in 8). Chunk = 128 K-floats (32 f4/row).
// step s: layer0 t=s (s<512), layer1 t=s-1 (s>=1); both MAC the h1[s-1] tile.
__global__ void __launch_bounds__(NTHREADS, 1)
gru_fused(const int* __restrict__ texts, const float* __restrict__ emb,
          const float* __restrict__ Wih0, const float* __restrict__ Whh0,
          const float* __restrict__ bih0, const float* __restrict__ bhh0,
          const float* __restrict__ Wih1, const float* __restrict__ Whh1,
          const float* __restrict__ bih1, const float* __restrict__ bhh1)
{
    extern __shared__ float4 smem[];
    float4* w_ih0 = smem;                               // 12*96  = 1152 f4
    float4* w_hh0 = smem + 12 * WIH0_S;                 // 12*128 = 1536 f4
    float4* w_ih1 = w_hh0 + 12 * WH_S;
    float4* w_hh1 = w_ih1 + 12 * WH_S;
    float4* tiles = w_hh1 + 12 * WH_S;                  // 2 x 2112 f4
    __shared__ float pool_sh[32];
    __shared__ int   tok_sh[BATCH];

    const int tid = threadIdx.x;
    const int bid = blockIdx.x;
    const int j0  = bid * 4;
    const int kq  = tid & 7;           // lane bits 0-2: K-slice
    const int jj  = (tid >> 3) & 3;    // lane bits 3-4: unit
    const int bg  = tid >> 5;          // warp id: batch group (8 batches)
    const int j   = j0 + jj;
    const int b0  = bg * 8;

    const unsigned base = *(volatile unsigned*)&g_flags[bid];

    // ---- stage weights (once) ----
    for (int idx = tid; idx < 12 * WIH0_S; idx += NTHREADS) {
        int m = idx / WIH0_S, f4 = idx - m * WIH0_S;
        int g = m >> 2, u = m & 3;
        float4 v = make_float4(0.f, 0.f, 0.f, 0.f);
        if (f4 < 75)
            v = reinterpret_cast<const float4*>(Wih0 + (size_t)(g * HDIM + j0 + u) * EDIM)[f4];
        w_ih0[idx] = v;
    }
    stage128(w_hh0, Whh0, j0, tid);
    stage128(w_ih1, Wih1, j0, tid);
    stage128(w_hh1, Whh1, j0, tid);

    const float br0 = bih0[j] + bhh0[j];
    const float bz0 = bih0[HDIM + j] + bhh0[HDIM + j];
    const float bx0 = bih0[2 * HDIM + j];
    const float bh0 = bhh0[2 * HDIM + j];
    const float br1 = bih1[j] + bhh1[j];
    const float bz1 = bih1[HDIM + j] + bhh1[HDIM + j];
    const float bx1 = bih1[2 * HDIM + j];
    const float bh1 = bhh1[2 * HDIM + j];

    // per-thread weight row pointers (1 ull2 == 1 f4), +kq base; chunk +32 f4
    const ulonglong2* eR  = (const ulonglong2*)w_ih0 + (0 + jj) * WIH0_S + kq;
    const ulonglong2* eZ  = (const ulonglong2*)w_ih0 + (4 + jj) * WIH0_S + kq;
    const ulonglong2* eN  = (const ulonglong2*)w_ih0 + (8 + jj) * WIH0_S + kq;
    const ulonglong2* hR0 = (const ulonglong2*)w_hh0 + (0 + jj) * WH_S + kq;
    const ulonglong2* hZ0 = (const ulonglong2*)w_hh0 + (4 + jj) * WH_S + kq;
    const ulonglong2* hN0 = (const ulonglong2*)w_hh0 + (8 + jj) * WH_S + kq;
    const ulonglong2* xR1 = (const ulonglong2*)w_ih1 + (0 + jj) * WH_S + kq;
    const ulonglong2* xZ1 = (const ulonglong2*)w_ih1 + (4 + jj) * WH_S + kq;
    const ulonglong2* xN1 = (const ulonglong2*)w_ih1 + (8 + jj) * WH_S + kq;
    const ulonglong2* hR1 = (const ulonglong2*)w_hh1 + (0 + jj) * WH_S + kq;
    const ulonglong2* hZ1 = (const ulonglong2*)w_hh1 + (4 + jj) * WH_S + kq;
    const ulonglong2* hN1 = (const ulonglong2*)w_hh1 + (8 + jj) * WH_S + kq;

    // SMEM u32 addresses of the two tile buffers (for cp.async)
    const uint32_t tile_u32_0 = (uint32_t)__cvta_generic_to_shared(tiles);
    const uint32_t tile_u32_1 = (uint32_t)__cvta_generic_to_shared(tiles + TILE_F4);

    // per-thread staging slots: 8 f4 per chunk; idx = tid + i*256
    // rr = idx>>5 (row), f4 = idx&31 (col within 32-f4 chunk)
    const float4* emb4 = (const float4*)emb;

#define DSTU32(QI, I) (((QI) & 1 ? tile_u32_1 : tile_u32_0) +                     \
        ((((tid + (I) * NTHREADS) >> 5) * TILE_S + ((tid + (I) * NTHREADS) & 31)) << 4))
#define STAGE_EMB(CC, QI) do { int c_ = (CC);                                    \
    _Pragma("unroll") for (int i = 0; i < 8; i++) {                              \
        int idx = tid + i * NTHREADS; int rr = idx >> 5, f4 = idx & 31;          \
        int gf4 = c_ * 32 + f4;                                                  \
        const float4* sp = emb4 + (size_t)tok_sh[rr] * 75 + (gf4 < 75 ? gf4 : 0);\
        cp16(DSTU32(QI, i), sp, gf4 < 75 ? 16u : 0u); }                          \
    cp_commit(); } while (0)
#define STAGE_H(SRC4, CC, QI) do { int c_ = (CC);                                \
    _Pragma("unroll") for (int i = 0; i < 8; i++) {                              \
        int idx = tid + i * NTHREADS; int rr = idx >> 5, f4 = idx & 31;          \
        cp16(DSTU32(QI, i), (SRC4) + rr * 128 + c_ * 32 + f4, 16u); }            \
    cp_commit(); } while (0)
#define CHUNK_READY() do { cp_wait0(); __syncthreads(); } while (0)
#define TPTR(QI) ((const ulonglong2*)(tiles + ((QI) & 1) * TILE_F4) + b0 * TILE_S + kq)

    for (int s = 0; s <= T_STEPS; s++) {
        const bool do0 = (s < T_STEPS);
        const bool do1 = (s >= 1);
        const float* h1prev = (s == 0) ? g_zero : g_h1 + (size_t)(s - 1) * BH;
        const float* h2prev = (s <= 1) ? g_zero : g_h2 + (size_t)(s - 2) * BH;
        const float4* h1p4 = (const float4*)h1prev;
        const float4* h2p4 = (const float4*)h2prev;

        if (do0 && tid < BATCH) tok_sh[tid] = texts[s * BATCH + tid];
        __syncthreads();     // tok visible; closes last step's tile/pool use

        ull AR[8], AZ[8], AX[8], AH[8];
#pragma unroll
        for (int i = 0; i < 8; i++) { AR[i] = AZ[i] = AX[i] = AH[i] = 0ull; }

        int qi = 0;

        // ---- phase A: embedding projection (pre-barrier: hides grid wait) ----
        if (do0) {
            STAGE_EMB(0, 0);
            for (int c = 0; c < 3; c++) {
                CHUNK_READY();
                if (c < 2) STAGE_EMB(c + 1, qi + 1);
                mac3x8(TPTR(qi), eR + c * 32, eZ + c * 32, eN + c * 32, AR, AZ, AX);
                qi++;
            }
        }

        // ---- grid wait: h1[s-1], h2[s-2] now published by all CTAs ----
        if (tid < NBLK) {
            unsigned tgt = base + (unsigned)s;
            while ((int)(*(volatile unsigned*)&g_flags[tid] - tgt) < 0) { }
            __threadfence();     // acquire
        }
        __syncthreads();

        ull BR[8], BZ[8], BX[8];
#pragma unroll
        for (int i = 0; i < 8; i++) { BR[i] = BZ[i] = BX[i] = 0ull; }

        // ---- phase B: shared h1[s-1] tile -> layer0-rec + layer1-in ----
        STAGE_H(h1p4, 0, qi);
        for (int c = 0; c < 4; c++) {
            CHUNK_READY();
            if (c < 3)       STAGE_H(h1p4, c + 1, qi + 1);
            else if (do1)    STAGE_H(h2p4, 0, qi + 1);
            mac6x8(TPTR(qi), hR0 + c * 32, hZ0 + c * 32, hN0 + c * 32,
                             xR1 + c * 32, xZ1 + c * 32, xN1 + c * 32,
                   AR, AZ, AH, BR, BZ, BX);
            qi++;
        }

        // ---- retire layer0 now: frees 64 acc regs before phase C ----
        if (do0) {
#pragma unroll
            for (int i = 0; i < 8; i++) {
                float fr = redq(AR[i]);
                float fz = redq(AZ[i]);
                float fx = redq(AX[i]);
                float fh = redq(AH[i]);
                if (kq == 0) {
                    int b = b0 + i;
                    float r = sigf(fr + br0);
                    float z = sigf(fz + bz0);
                    float n = tanhf(fx + bx0 + r * (fh + bh0));
                    float hp = h1prev[b * HDIM + j];
                    g_h1[(size_t)s * BH + b * HDIM + j] = (1.0f - z) * n + z * hp;
                }
            }
        }

        // ---- phase C: h2[s-2] tile -> layer1 recurrent ----
        if (do1) {
            ull BHa[8];
#pragma unroll
            for (int i = 0; i < 8; i++) BHa[i] = 0ull;
            for (int c = 0; c < 4; c++) {
                CHUNK_READY();
                if (c < 3) STAGE_H(h2p4, c + 1, qi + 1);
                mac3x8(TPTR(qi), hR1 + c * 32, hZ1 + c * 32, hN1 + c * 32, BR, BZ, BHa);
                qi++;
            }

            float psum = 0.f;
#pragma unroll
            for (int i = 0; i < 8; i++) {
                float fr = redq(BR[i]);
                float fz = redq(BZ[i]);
                float fx = redq(BX[i]);
                float fh = redq(BHa[i]);
                if (kq == 0) {
                    int b = b0 + i;
                    float r = sigf(fr + br1);
                    float z = sigf(fz + bz1);
                    float n = tanhf(fx + bx1 + r * (fh + bh1));
                    float hp = h2prev[b * HDIM + j];
                    float hnew = (1.0f - z) * n + z * hp;
                    g_h2[(size_t)(s - 1) * BH + b * HDIM + j] = hnew;
                    psum += hnew;
                }
            }
            if (kq == 0) pool_sh[bg * 4 + jj] = psum;   // 32 slots
            __syncthreads();
            if (tid < 4) {
                float sum = 0.f;
#pragma unroll
                for (int g = 0; g < 8; g++) sum += pool_sh[g * 4 + tid];
                g_pooled[(s - 1) * HDIM + j0 + tid] = sum * (1.0f / BATCH);
            }
        }

        // ---- arrive ----
        __threadfence();
        __syncthreads();
        if (tid == 0)
            *(volatile unsigned*)&g_flags[bid] = base + (unsigned)s + 1u;
    }
#undef DSTU32
#undef STAGE_EMB
#undef STAGE_H
#undef CHUNK_READY
#undef TPTR
}

// =====================  final FC: [T,H] @ [L,H]^T + b  ======================
__global__ void fc_kernel(const float* __restrict__ fcW, const float* __restrict__ fcb,
                          float* __restrict__ out)
{
    int t    = blockIdx.x;
    int l    = threadIdx.x >> 5;   // 5 warps -> 5 outputs
    int lane = threadIdx.x & 31;
    const float* p = g_pooled + t * HDIM;
    const float* w = fcW + l * HDIM;
    float s = 0.f;
#pragma unroll 4
    for (int k = lane; k < HDIM; k += 32) s += p[k] * w[k];
#pragma unroll
    for (int o = 16; o; o >>= 1) s += __shfl_xor_sync(0xffffffffu, s, o);
    if (lane == 0) out[t * 5 + l] = s + fcb[l];
}

// ===========================================================================
extern "C" void kernel_launch(void* const* d_in, const int* in_sizes, int n_in,
                              void* d_out, int out_size) {
    (void)in_sizes; (void)n_in; (void)out_size;
    const int*   texts = (const int*)  d_in[0];
    const float* emb   = (const float*)d_in[1];
    const float* Wih0  = (const float*)d_in[2];
    const float* Whh0  = (const float*)d_in[3];
    const float* bih0  = (const float*)d_in[4];
    const float* bhh0  = (const float*)d_in[5];
    const float* Wih1  = (const float*)d_in[6];
    const float* Whh1  = (const float*)d_in[7];
    const float* bih1  = (const float*)d_in[8];
    const float* bhh1  = (const float*)d_in[9];
    const float* fcW   = (const float*)d_in[10];
    const float* fcb   = (const float*)d_in[11];
    float* out = (float*)d_out;

    // 1152 + 3*1536 + 2*2112 = 9984 float4 = 159,744 B dynamic SMEM
    const int smemB = (12 * WIH0_S + 3 * 12 * WH_S + 2 * TILE_F4) * 16;
    cudaFuncSetAttribute(gru_fused, cudaFuncAttributeMaxDynamicSharedMemorySize, smemB);

    gru_fused<<<NBLK, NTHREADS, smemB>>>(texts, emb,
                                         Wih0, Whh0, bih0, bhh0,
                                         Wih1, Whh1, bih1, bhh1);
    fc_kernel<<<T_STEPS, 160>>>(fcW, fcb, out);
}